// round 4
// baseline (speedup 1.0000x reference)
#include <cuda_runtime.h>

#define SEQ   65536
#define HID   1024
#define MVBLK 4096            // matvec grid (16 rows/block)
#define EPI_B 128             // epilogue grid (co-resident, <=148 SMs)
#define EPI_T 256             // epilogue block size
#define SLICE (SEQ / EPI_B)   // 512 elements per epilogue block

// ── Scratch (allocation-free __device__ globals) ────────────────────────
__device__ float g_energies[SEQ];
__device__ float g_exps[SEQ];
__device__ float g_blockmax[MVBLK];
__device__ float g_max_part[EPI_B];
__device__ float g_sum_part[EPI_B];

// Self-resetting grid barrier state (counter returns to 0; gen monotonic)
__device__ unsigned g_cnt = 0;
__device__ volatile unsigned g_gen = 0;

__device__ __forceinline__ void gridbar(unsigned& local_gen) {
    __syncthreads();
    if (threadIdx.x == 0) {
        unsigned my = local_gen;
        __threadfence();
        if (atomicAdd(&g_cnt, 1u) == gridDim.x - 1) {
            g_cnt = 0;
            __threadfence();
            g_gen = my + 1;            // release
        } else {
            while (g_gen == my) { __nanosleep(64); }   // backoff spin
        }
        local_gen = my + 1;
    }
    __syncthreads();
}

// ── Kernel 1: matvec. One warp per row; 16 warps/block; grid 4096. ──────
__global__ __launch_bounds__(512) void matvec_kernel(
    const float* __restrict__ hidden,
    const float* __restrict__ enc)
{
    __shared__ float sh[HID];
    __shared__ float wmax[16];

    for (int i = threadIdx.x; i < HID / 4; i += blockDim.x)
        ((float4*)sh)[i] = ((const float4*)hidden)[i];
    __syncthreads();

    const int warp = threadIdx.x >> 5;
    const int lane = threadIdx.x & 31;
    const int row  = blockIdx.x * 16 + warp;

    const float4* __restrict__ rp = (const float4*)(enc + (size_t)row * HID);
    const float4* __restrict__ hp = (const float4*)sh;

    float acc = 0.f;
#pragma unroll
    for (int k = 0; k < HID / 128; k++) {           // 8 independent LDG.128
        float4 a = __ldcs(&rp[lane + k * 32]);      // streaming: no reuse
        float4 b = hp[lane + k * 32];
        acc += a.x * b.x + a.y * b.y + a.z * b.z + a.w * b.w;
    }
#pragma unroll
    for (int o = 16; o; o >>= 1)
        acc += __shfl_xor_sync(0xFFFFFFFFu, acc, o);

    if (lane == 0) {
        g_energies[row] = acc;
        wmax[warp] = acc;
    }
    __syncthreads();

    if (threadIdx.x == 0) {
        float m = wmax[0];
#pragma unroll
        for (int i = 1; i < 16; i++) m = fmaxf(m, wmax[i]);
        g_blockmax[blockIdx.x] = m;                 // plain store, no atomics
    }
}

// ── Kernel 2: epilogue. grid=128 blocks, 2 grid barriers, no atomics
//    on data (fixed-order reductions → deterministic). ───────────────────
__global__ __launch_bounds__(EPI_T) void epilogue_kernel(float4* __restrict__ out)
{
    unsigned gen = g_gen;   // all threads read; only thread0 uses/updates
    const int b = blockIdx.x;
    const int t = threadIdx.x;

    __shared__ float warp_part[EPI_T / 32];

    // Phase 0: each block reduces its 32 block-maxes (warp 0 only)
    if (t < 32) {
        float m = g_blockmax[b * 32 + t];
#pragma unroll
        for (int o = 16; o; o >>= 1)
            m = fmaxf(m, __shfl_xor_sync(0xFFFFFFFFu, m, o));
        if (t == 0) g_max_part[b] = m;
    }

    gridbar(gen);

    // Global max: every thread reduces 128 partials (L1 broadcast)
    float mx = g_max_part[0];
#pragma unroll 16
    for (int i = 1; i < EPI_B; i++) mx = fmaxf(mx, g_max_part[i]);

    // Phase 1: partial exp-sum over this block's 512-element slice
    const int base = b * SLICE;           // 512 elements = 128 float4
    float acc = 0.f;
    {
        const int i0 = base + t * 2;      // 256 threads, 2 elements each
        float e0 = expf(g_energies[i0]     - mx);
        float e1 = expf(g_energies[i0 + 1] - mx);
        g_exps[i0]     = e0;
        g_exps[i0 + 1] = e1;
        acc = e0 + e1;
    }
#pragma unroll
    for (int o = 16; o; o >>= 1)
        acc += __shfl_xor_sync(0xFFFFFFFFu, acc, o);
    if ((t & 31) == 0) warp_part[t >> 5] = acc;
    __syncthreads();
    if (t == 0) {
        float s = 0.f;
#pragma unroll
        for (int i = 0; i < EPI_T / 32; i++) s += warp_part[i];
        g_sum_part[b] = s;
    }

    gridbar(gen);

    // Global sum in FIXED order (deterministic), then normalize the slice
    float s = 0.f;
#pragma unroll 16
    for (int i = 0; i < EPI_B; i++) s += g_sum_part[i];
    const float inv = 1.0f / s;

    // 128 float4 stores per block: threads 0..127 handle one float4 each
    if (t < SLICE / 4) {
        const int i4 = base / 4 + t;
        float4 e = ((const float4*)g_exps)[i4];
        e.x *= inv; e.y *= inv; e.z *= inv; e.w *= inv;
        out[i4] = e;
    }
}

extern "C" void kernel_launch(void* const* d_in, const int* in_sizes, int n_in,
                              void* d_out, int out_size)
{
    const float* hidden;
    const float* enc;
    if (in_sizes[0] == HID) {
        hidden = (const float*)d_in[0];
        enc    = (const float*)d_in[1];
    } else {
        hidden = (const float*)d_in[1];
        enc    = (const float*)d_in[0];
    }
    float4* out = (float4*)d_out;

    matvec_kernel<<<MVBLK, 512>>>(hidden, enc);
    epilogue_kernel<<<EPI_B, EPI_T>>>(out);
}